// round 2
// baseline (speedup 1.0000x reference)
#include <cuda_runtime.h>

// ---------------------------------------------------------------------------
// NeuralODE: Bosh3 fixed-step integrator, persistent-CTA fp32 kernel.
// B=2048 rows, L=128 state, P=8 params, W=512 hidden, T=128 saves.
// Each CTA owns 16 batch rows for the entire integration (rows independent).
// Weights pre-transposed to [K][N] once; streamed L2->smem via cp.async,
// double-buffered. Inner product uses packed fma.rn.f32x2 (FFMA2).
// ---------------------------------------------------------------------------

#define BB 2048
#define LL 128
#define PP 8
#define WW 512
#define TT 128
#define K0 136          // L + P
#define BR 16           // batch rows per CTA
#define NTHREADS 256
#define NCTAS (BB / BR) // 128

// Transposed weights in device scratch (allocation-free rule: __device__ globals)
__device__ float g_W0t[K0 * WW];   // [136][512]
__device__ float g_W1t[WW * WW];   // [512][512]
__device__ float g_W2t[WW * LL];   // [512][128]

// smem layout (floats)
#define SM_IN    0
#define SM_H1    (SM_IN + BR * K0)        // 2176
#define SM_H2    (SM_H1 + BR * WW)        // +8192
#define SM_Y     (SM_H2 + BR * WW)        // +8192
#define SM_K1    (SM_Y  + BR * LL)        // +2048
#define SM_K2    (SM_K1 + BR * LL)
#define SM_K3    (SM_K2 + BR * LL)
#define SM_WT    (SM_K3 + BR * LL)        // 2 x 8192 double buffer
#define SM_FLOATS (SM_WT + 2 * 8192)
#define SMEM_BYTES (SM_FLOATS * 4)        // 172544

// ---------------- packed f32x2 helpers ----------------
__device__ __forceinline__ unsigned long long fma2(unsigned long long a,
                                                   unsigned long long b,
                                                   unsigned long long c) {
    unsigned long long d;
    asm("fma.rn.f32x2 %0, %1, %2, %3;" : "=l"(d) : "l"(a), "l"(b), "l"(c));
    return d;
}
__device__ __forceinline__ unsigned long long pack2(float x, float y) {
    unsigned long long d;
    asm("mov.b64 %0, {%1, %2};" : "=l"(d) : "f"(x), "f"(y));
    return d;
}
__device__ __forceinline__ float2 unpack2(unsigned long long v) {
    float2 r;
    asm("mov.b64 {%0, %1}, %2;" : "=f"(r.x), "=f"(r.y) : "l"(v));
    return r;
}

// ---------------- cp.async helpers ----------------
__device__ __forceinline__ void cp16(float* smem_dst, const float* gsrc) {
    unsigned sa = (unsigned)__cvta_generic_to_shared(smem_dst);
    asm volatile("cp.async.cg.shared.global [%0], [%1], 16;" :: "r"(sa), "l"(gsrc));
}
__device__ __forceinline__ void cp_commit() {
    asm volatile("cp.async.commit_group;");
}

// ---------------------------------------------------------------------------
// One dense layer: O[BR][N] = act(A[BR][K] @ Wt[K][N] + bias)
// Wt is [K][N] row-major in global (pre-transposed). Weight tiles of KT rows
// are staged to smem via cp.async (double buffered).
// Thread mapping: warp w owns rows 2w, 2w+1; lane owns G = N/128 column
// groups, 4 contiguous cols per group at n = g*128 + lane*4 (conflict-free
// LDS.128 on the weight tile).
// ---------------------------------------------------------------------------
template <int K, int N, int KT, bool ACT>
__device__ __forceinline__ void layer(const float* __restrict__ A, int lda,
                                      const float* __restrict__ Wt,
                                      const float* __restrict__ bias,
                                      float* __restrict__ O,
                                      float* __restrict__ wtile, int tid) {
    constexpr int G    = N / 128;   // float4 column groups per lane (4 or 1)
    constexpr int NT   = K / KT;    // number of K tiles
    constexpr int TILE = KT * N;    // floats per weight tile
    constexpr int WBUF = 8192;      // float stride between the two buffers

    const int lane = tid & 31;
    const int warp = tid >> 5;
    const int r0   = warp * 2;

    unsigned long long acc0[2 * G];
    unsigned long long acc1[2 * G];
#pragma unroll
    for (int j = 0; j < 2 * G; ++j) { acc0[j] = 0ull; acc1[j] = 0ull; }

    // stage tile 0 into buffer 0
    for (int i = tid; i < TILE / 4; i += NTHREADS) cp16(wtile + 4 * i, Wt + 4 * i);
    cp_commit();

    for (int kt = 0; kt < NT; ++kt) {
        __syncthreads();  // all threads done reading the buffer we are about to refill
        if (kt + 1 < NT) {
            const float* src = Wt + (size_t)(kt + 1) * TILE;
            float* dst = wtile + ((kt + 1) & 1) * WBUF;
            for (int i = tid; i < TILE / 4; i += NTHREADS) cp16(dst + 4 * i, src + 4 * i);
            cp_commit();
            asm volatile("cp.async.wait_group 1;");
        } else {
            asm volatile("cp.async.wait_group 0;");
        }
        __syncthreads();  // staged data visible to all threads

        const float* wb  = wtile + (kt & 1) * WBUF;
        const float* Ar0 = A + r0 * lda + kt * KT;
        const float* Ar1 = Ar0 + lda;
#pragma unroll
        for (int kk = 0; kk < KT; ++kk) {
            const float a0 = Ar0[kk];            // smem broadcast
            const float a1 = Ar1[kk];
            const unsigned long long a0p = pack2(a0, a0);
            const unsigned long long a1p = pack2(a1, a1);
            const float* wrow = wb + kk * N;
#pragma unroll
            for (int g = 0; g < G; ++g) {
                const ulonglong2 w =
                    *reinterpret_cast<const ulonglong2*>(wrow + g * 128 + lane * 4);
                acc0[2 * g]     = fma2(a0p, w.x, acc0[2 * g]);
                acc1[2 * g]     = fma2(a1p, w.x, acc1[2 * g]);
                acc0[2 * g + 1] = fma2(a0p, w.y, acc0[2 * g + 1]);
                acc1[2 * g + 1] = fma2(a1p, w.y, acc1[2 * g + 1]);
            }
        }
    }

    // epilogue: bias + (optional) tanh, float4 stores (conflict-free)
#pragma unroll
    for (int g = 0; g < G; ++g) {
        const int n = g * 128 + lane * 4;
        const float4 bv = *reinterpret_cast<const float4*>(bias + n);
        float2 p00 = unpack2(acc0[2 * g]);
        float2 p01 = unpack2(acc0[2 * g + 1]);
        float2 p10 = unpack2(acc1[2 * g]);
        float2 p11 = unpack2(acc1[2 * g + 1]);
        float4 v0 = make_float4(p00.x + bv.x, p00.y + bv.y, p01.x + bv.z, p01.y + bv.w);
        float4 v1 = make_float4(p10.x + bv.x, p10.y + bv.y, p11.x + bv.z, p11.y + bv.w);
        if (ACT) {
            v0.x = tanhf(v0.x); v0.y = tanhf(v0.y); v0.z = tanhf(v0.z); v0.w = tanhf(v0.w);
            v1.x = tanhf(v1.x); v1.y = tanhf(v1.y); v1.z = tanhf(v1.z); v1.w = tanhf(v1.w);
        }
        *reinterpret_cast<float4*>(O + r0 * N + n)       = v0;
        *reinterpret_cast<float4*>(O + (r0 + 1) * N + n) = v1;
    }
    __syncthreads();  // outputs visible; safe for caller to read / next layer to stage
}

// ---------------------------------------------------------------------------
// One-time weight transpose: W[N][K] (row-major, K contiguous) -> Wt[K][N]
// ---------------------------------------------------------------------------
__global__ void transpose_all_kernel(const float* __restrict__ W0,
                                     const float* __restrict__ W1,
                                     const float* __restrict__ W2) {
    int idx = blockIdx.x * blockDim.x + threadIdx.x;
    const int t0 = K0 * WW, t1 = WW * WW, t2 = WW * LL;
    if (idx < t0) {
        int k = idx / WW, n = idx % WW;
        g_W0t[idx] = W0[n * K0 + k];
        return;
    }
    idx -= t0;
    if (idx < t1) {
        int k = idx / WW, n = idx % WW;
        g_W1t[idx] = W1[n * WW + k];
        return;
    }
    idx -= t1;
    if (idx < t2) {
        int k = idx / LL, n = idx % LL;
        g_W2t[idx] = W2[n * WW + k];
    }
}

// ---------------------------------------------------------------------------
// Persistent integrator kernel
// ---------------------------------------------------------------------------
__global__ __launch_bounds__(NTHREADS) void ode_kernel(
    const float* __restrict__ x0, const float* __restrict__ ts,
    const float* __restrict__ args,
    const float* __restrict__ b0, const float* __restrict__ b1,
    const float* __restrict__ b2, float* __restrict__ out) {
    extern __shared__ float sm[];
    float* in_sm = sm + SM_IN;
    float* h1    = sm + SM_H1;
    float* h2    = sm + SM_H2;
    float* ys    = sm + SM_Y;
    float* kbuf0 = sm + SM_K1;
    float* kbuf1 = sm + SM_K2;
    float* kbuf2 = sm + SM_K3;
    float* wtile = sm + SM_WT;

    const int tid  = threadIdx.x;
    const int row0 = blockIdx.x * BR;

    // args -> in_sm[:, 128:136] (set once, constant over integration)
    for (int i = tid; i < BR * PP; i += NTHREADS) {
        int r = i / PP, p = i % PP;
        in_sm[r * K0 + LL + p] = args[(size_t)(row0 + r) * PP + p];
    }
    // y = x0 ; out[:, 0, :] = x0
    for (int i = tid; i < BR * LL; i += NTHREADS) {
        int r = i / LL, l = i % LL;
        float v = x0[(size_t)(row0 + r) * LL + l];
        ys[i] = v;
        out[(size_t)(row0 + r) * TT * LL + l] = v;
    }
    // (first layer's internal barriers order these writes before any read)

    for (int t = 0; t < TT - 1; ++t) {
        const float dt = ts[t + 1] - ts[t];

        // three vf stages: k1 = f(y); k2 = f(y + 0.5 dt k1); k3 = f(y + 0.75 dt k2)
        for (int s = 0; s < 3; ++s) {
            const float c = (s == 0) ? 0.0f : (s == 1 ? 0.5f * dt : 0.75f * dt);
            const float* ksrc = (s == 0) ? ys : (s == 1 ? kbuf0 : kbuf1);
            float* kdst       = (s == 0) ? kbuf0 : (s == 1 ? kbuf1 : kbuf2);
            // in_sm[:, :128] = y + c * ksrc   (same-thread element mapping; the
            // layer's internal __syncthreads orders it against compute)
            for (int i = tid; i < BR * LL; i += NTHREADS) {
                int r = i / LL, l = i % LL;
                in_sm[r * K0 + l] = ys[i] + c * ksrc[i];
            }
            layer<K0, WW, 8,  true >(in_sm, K0, g_W0t, b0, h1,   wtile, tid);
            layer<WW, WW, 16, true >(h1,    WW, g_W1t, b1, h2,   wtile, tid);
            layer<WW, LL, 16, false>(h2,    WW, g_W2t, b2, kdst, wtile, tid);
        }

        // y += dt*(2/9 k1 + 1/3 k2 + 4/9 k3); save
        const float d1 = dt * (2.0f / 9.0f);
        const float d2 = dt * (1.0f / 3.0f);
        const float d3 = dt * (4.0f / 9.0f);
        for (int i = tid; i < BR * LL; i += NTHREADS) {
            int r = i / LL, l = i % LL;
            float v = ys[i] + d1 * kbuf0[i] + d2 * kbuf1[i] + d3 * kbuf2[i];
            ys[i] = v;
            out[(size_t)(row0 + r) * TT * LL + (size_t)(t + 1) * LL + l] = v;
        }
        // no barrier needed: next stage's fill reads ys[i]/k[i] with the same
        // per-thread index mapping, and the first layer barriers before compute
    }
}

// ---------------------------------------------------------------------------
extern "C" void kernel_launch(void* const* d_in, const int* in_sizes, int n_in,
                              void* d_out, int out_size) {
    (void)in_sizes; (void)n_in; (void)out_size;
    const float* x0   = (const float*)d_in[0];
    const float* ts   = (const float*)d_in[1];
    const float* args = (const float*)d_in[2];
    const float* W0   = (const float*)d_in[3];
    const float* b0   = (const float*)d_in[4];
    const float* W1   = (const float*)d_in[5];
    const float* b1   = (const float*)d_in[6];
    const float* W2   = (const float*)d_in[7];
    const float* b2   = (const float*)d_in[8];
    float* out = (float*)d_out;

    const int total = K0 * WW + WW * WW + WW * LL;
    transpose_all_kernel<<<(total + 255) / 256, 256>>>(W0, W1, W2);

    cudaFuncSetAttribute(ode_kernel, cudaFuncAttributeMaxDynamicSharedMemorySize,
                         SMEM_BYTES);
    ode_kernel<<<NCTAS, NTHREADS, SMEM_BYTES>>>(x0, ts, args, b0, b1, b2, out);
}

// round 4
// speedup vs baseline: 1.0281x; 1.0281x over previous
#include <cuda_runtime.h>

// ---------------------------------------------------------------------------
// NeuralODE Bosh3 fixed-step integrator, persistent-CTA fp32 kernel, v2.
// B=2048, L=128, P=8, W=512, T=128. 128 CTAs x 256 threads; each CTA owns
// 16 batch rows for the whole integration.
//
// v2 changes vs v1 (which was smem-crossbar bound: L1=68%, fma=30%):
//  - Weight layout pre-transformed to k-PAIR interleave [k/2][N][2] so one
//    16B smem load yields (w_k, w_k+1) per column and one 16B broadcast load
//    yields (a_k..a_k+3); fma.rn.f32x2 accumulates even/odd-k partial sums
//    (reduced in epilogue). No pack movs in the inner loop.
//  - Warp owns 8 rows x 128 cols (N=512) / 4 rows x 64 cols (N=128):
//    4x fewer weight smem reads per FMA than v1.
//  - RK stage glue fused into final-layer epilogues.
//  - Bigger K tiles (fewer barriers).
// (R3 resubmission: R3 bench was an infra failure; kernel never ran.)
// ---------------------------------------------------------------------------

#define BB 2048
#define LL 128
#define PP 8
#define WW 512
#define TT 128
#define K0 136          // L + P
#define BR 16           // batch rows per CTA
#define NTHREADS 256
#define NCTAS (BB / BR) // 128

// pair-interleaved weights: [k/2][N][2]
__device__ float g_W0p[K0 * WW];   // pairs: 68  x 512 x 2
__device__ float g_W1p[WW * WW];   // pairs: 256 x 512 x 2
__device__ float g_W2p[WW * LL];   // pairs: 256 x 128 x 2

// smem layout (floats)
#define SM_IN    0
#define SM_H1    (SM_IN + BR * K0)          // +2176
#define SM_H2    (SM_H1 + BR * WW)          // +8192
#define SM_Y     (SM_H2 + BR * WW)          // +8192
#define SM_K1    (SM_Y  + BR * LL)          // +2048
#define SM_K2    (SM_K1 + BR * LL)          // +2048
#define SM_WT    (SM_K2 + BR * LL)          // +2048 -> 24704
#define WBUF     16384                       // floats per weight buffer (64KB)
#define SM_FLOATS (SM_WT + 2 * WBUF)         // 57472
#define SMEM_BYTES (SM_FLOATS * 4)           // 229888  (<= 232448 opt-in)

// ---------------- packed f32x2 helpers ----------------
__device__ __forceinline__ unsigned long long fma2(unsigned long long a,
                                                   unsigned long long b,
                                                   unsigned long long c) {
    unsigned long long d;
    asm("fma.rn.f32x2 %0, %1, %2, %3;" : "=l"(d) : "l"(a), "l"(b), "l"(c));
    return d;
}
__device__ __forceinline__ float2 unpack2(unsigned long long v) {
    float2 r;
    asm("mov.b64 {%0, %1}, %2;" : "=f"(r.x), "=f"(r.y) : "l"(v));
    return r;
}
__device__ __forceinline__ float red2(unsigned long long v) {
    float2 r = unpack2(v);
    return r.x + r.y;
}

// ---------------- cp.async helpers ----------------
__device__ __forceinline__ void cp16(float* smem_dst, const float* gsrc) {
    unsigned sa = (unsigned)__cvta_generic_to_shared(smem_dst);
    asm volatile("cp.async.cg.shared.global [%0], [%1], 16;" :: "r"(sa), "l"(gsrc));
}
__device__ __forceinline__ void cp_commit() {
    asm volatile("cp.async.commit_group;");
}

// epilogue context
struct Epi {
    float* in_sm;        // [BR][K0]
    float* ys;           // [BR][LL]
    const float* k1;     // [BR][LL]
    const float* k2;     // [BR][LL]
    float* kdst;         // [BR][LL]   (EPI 1)
    float* outp;         // out + row0g*TT*LL + (t+1)*LL   (EPI 2)
    float c, d1, d2, d3;
};

// ---------------------------------------------------------------------------
// O[BR][N] = act(A[BR][K] @ W + bias), weights in pair-interleaved global
// layout Wg[(k/2)*N*2 + n*2 + (k&1)], staged to smem in KT-row tiles
// (double buffered, cp.async).
//
// Warp mapping: NRG = BR/R row groups; warp%NRG -> row group of R rows;
// warp/NRG -> column span of 32*VEC cols; lane -> VEC contiguous cols.
// Accumulator acc[r][v] is f32x2: .x = even-k partial, .y = odd-k partial.
//
// EPI: 0 = tanh -> O.  1 = kdst=v, in_sm = ys + c*v.
//      2 = y' = ys + d1*k1 + d2*k2 + d3*v; ys/in_sm/out <- y'.
// ---------------------------------------------------------------------------
template <int K, int N, int KT, int R, int VEC, int EPI>
__device__ __forceinline__ void layer(const float* __restrict__ A, int lda,
                                      const float* __restrict__ Wg,
                                      const float* __restrict__ bias,
                                      float* __restrict__ O,
                                      float* __restrict__ wtile, int tid,
                                      const Epi& e) {
    constexpr int NT   = K / KT;
    constexpr int TILE = KT * N;         // floats per tile (pair layout, same count)
    constexpr int NRG  = BR / R;

    const int lane = tid & 31;
    const int warp = tid >> 5;
    const int row0 = (warp % NRG) * R;
    const int col0 = (warp / NRG) * (32 * VEC) + lane * VEC;

    unsigned long long acc[R][VEC];
#pragma unroll
    for (int r = 0; r < R; ++r)
#pragma unroll
        for (int v = 0; v < VEC; ++v) acc[r][v] = 0ull;

    // stage tile 0 into buffer 0
    for (int i = tid; i < TILE / 4; i += NTHREADS) cp16(wtile + 4 * i, Wg + 4 * i);
    cp_commit();

    for (int kt = 0; kt < NT; ++kt) {
        __syncthreads();                 // everyone done with buffer being refilled
        if (kt + 1 < NT) {
            const float* src = Wg + (size_t)(kt + 1) * TILE;
            float* dst = wtile + ((kt + 1) & 1) * WBUF;
            for (int i = tid; i < TILE / 4; i += NTHREADS) cp16(dst + 4 * i, src + 4 * i);
            cp_commit();
            asm volatile("cp.async.wait_group 1;");
        } else {
            asm volatile("cp.async.wait_group 0;");
        }
        __syncthreads();                 // staged tile visible

        const float* wb   = wtile + (kt & 1) * WBUF;
        const float* Arow = A + row0 * lda + kt * KT;   // float offset of k-base

        // each iteration covers 2 k-pairs (4 k values)
#pragma unroll 1
        for (int kp = 0; kp < KT / 2; kp += 2) {
            ulonglong2 a[R];             // .x = pair kp, .y = pair kp+1
#pragma unroll
            for (int r = 0; r < R; ++r)
                a[r] = *reinterpret_cast<const ulonglong2*>(Arow + r * lda + 2 * kp);
#pragma unroll
            for (int kk = 0; kk < 2; ++kk) {
                const float* wrow = wb + ((kp + kk) * N + col0) * 2;
                const ulonglong2 w01 = *reinterpret_cast<const ulonglong2*>(wrow);
                ulonglong2 w23;
                if (VEC == 4) w23 = *reinterpret_cast<const ulonglong2*>(wrow + 4);
#pragma unroll
                for (int r = 0; r < R; ++r) {
                    const unsigned long long av = kk ? a[r].y : a[r].x;
                    acc[r][0] = fma2(av, w01.x, acc[r][0]);
                    acc[r][1] = fma2(av, w01.y, acc[r][1]);
                    if (VEC == 4) {
                        acc[r][2] = fma2(av, w23.x, acc[r][2]);
                        acc[r][3] = fma2(av, w23.y, acc[r][3]);
                    }
                }
            }
        }
    }

    // ---- epilogue ----
    if (EPI == 0) {
#pragma unroll
        for (int r = 0; r < R; ++r) {
            const int row = row0 + r;
            if (VEC == 4) {
                const float4 bv = *reinterpret_cast<const float4*>(bias + col0);
                float4 v;
                v.x = tanhf(red2(acc[r][0]) + bv.x);
                v.y = tanhf(red2(acc[r][1]) + bv.y);
                v.z = tanhf(red2(acc[r][2]) + bv.z);
                v.w = tanhf(red2(acc[r][3]) + bv.w);
                *reinterpret_cast<float4*>(O + row * N + col0) = v;
            } else {
                const float2 bv = *reinterpret_cast<const float2*>(bias + col0);
                float2 v;
                v.x = tanhf(red2(acc[r][0]) + bv.x);
                v.y = tanhf(red2(acc[r][1]) + bv.y);
                *reinterpret_cast<float2*>(O + row * N + col0) = v;
            }
        }
    } else {
        // N == 128, VEC == 2 layers only
        const float2 bv = *reinterpret_cast<const float2*>(bias + col0);
#pragma unroll
        for (int r = 0; r < R; ++r) {
            const int row = row0 + r;
            const float v0 = red2(acc[r][0]) + bv.x;
            const float v1 = red2(acc[r][1]) + bv.y;
            const float2 yv = *reinterpret_cast<const float2*>(e.ys + row * LL + col0);
            if (EPI == 1) {
                *reinterpret_cast<float2*>(e.kdst + row * LL + col0) = make_float2(v0, v1);
                float2 iv = make_float2(yv.x + e.c * v0, yv.y + e.c * v1);
                *reinterpret_cast<float2*>(e.in_sm + row * K0 + col0) = iv;
            } else { // EPI == 2
                const float2 k1v = *reinterpret_cast<const float2*>(e.k1 + row * LL + col0);
                const float2 k2v = *reinterpret_cast<const float2*>(e.k2 + row * LL + col0);
                float2 yn;
                yn.x = yv.x + e.d1 * k1v.x + e.d2 * k2v.x + e.d3 * v0;
                yn.y = yv.y + e.d1 * k1v.y + e.d2 * k2v.y + e.d3 * v1;
                *reinterpret_cast<float2*>(e.ys + row * LL + col0) = yn;
                *reinterpret_cast<float2*>(e.in_sm + row * K0 + col0) = yn;
                *reinterpret_cast<float2*>(e.outp + (size_t)row * (TT * LL) + col0) = yn;
            }
        }
    }
    __syncthreads();   // outputs visible; safe for next layer to stage/read
}

// ---------------------------------------------------------------------------
// One-time weight transform: W[N][K] row-major -> pair-interleave [k/2][N][2]
// ---------------------------------------------------------------------------
__global__ void transform_kernel(const float* __restrict__ W0,
                                 const float* __restrict__ W1,
                                 const float* __restrict__ W2) {
    int idx = blockIdx.x * blockDim.x + threadIdx.x;
    const int t0 = K0 * WW, t1 = WW * WW, t2 = WW * LL;
    if (idx < t0) {
        int q = idx & 1, n = (idx >> 1) % WW, p = (idx >> 1) / WW;
        g_W0p[idx] = W0[n * K0 + 2 * p + q];
        return;
    }
    idx -= t0;
    if (idx < t1) {
        int q = idx & 1, n = (idx >> 1) % WW, p = (idx >> 1) / WW;
        g_W1p[idx] = W1[n * WW + 2 * p + q];
        return;
    }
    idx -= t1;
    if (idx < t2) {
        int q = idx & 1, n = (idx >> 1) % LL, p = (idx >> 1) / LL;
        g_W2p[idx] = W2[n * WW + 2 * p + q];
    }
}

// ---------------------------------------------------------------------------
// Persistent integrator kernel
// ---------------------------------------------------------------------------
__global__ __launch_bounds__(NTHREADS) void ode_kernel(
    const float* __restrict__ x0, const float* __restrict__ ts,
    const float* __restrict__ args,
    const float* __restrict__ b0, const float* __restrict__ b1,
    const float* __restrict__ b2, float* __restrict__ out) {
    extern __shared__ float sm[];
    float* in_sm = sm + SM_IN;
    float* h1    = sm + SM_H1;
    float* h2    = sm + SM_H2;
    float* ys    = sm + SM_Y;
    float* k1    = sm + SM_K1;
    float* k2    = sm + SM_K2;
    float* wtile = sm + SM_WT;

    const int tid   = threadIdx.x;
    const int row0g = blockIdx.x * BR;

    // args -> in_sm[:, 128:136] (constant over integration)
    for (int i = tid; i < BR * PP; i += NTHREADS) {
        int r = i / PP, p = i % PP;
        in_sm[r * K0 + LL + p] = args[(size_t)(row0g + r) * PP + p];
    }
    // y = x0 ; in = x0 ; out[:, 0, :] = x0
    for (int i = tid; i < BR * LL; i += NTHREADS) {
        int r = i / LL, l = i % LL;
        float v = x0[(size_t)(row0g + r) * LL + l];
        ys[i] = v;
        in_sm[r * K0 + l] = v;
        out[(size_t)(row0g + r) * TT * LL + l] = v;
    }
    // first layer's internal barrier (before tile-0 compute) orders these writes

    Epi e;
    e.in_sm = in_sm; e.ys = ys; e.k1 = k1; e.k2 = k2;

    for (int t = 0; t < TT - 1; ++t) {
        const float dt = ts[t + 1] - ts[t];

        // stage 0: k1 = f(y);  in <- y + 0.5*dt*k1
        e.kdst = k1; e.c = 0.5f * dt;
        layer<K0, WW, 8,  8, 4, 0>(in_sm, K0, g_W0p, b0, h1, wtile, tid, e);
        layer<WW, WW, 32, 8, 4, 0>(h1,    WW, g_W1p, b1, h2, wtile, tid, e);
        layer<WW, LL, 64, 4, 2, 1>(h2,    WW, g_W2p, b2, nullptr, wtile, tid, e);

        // stage 1: k2 = f(in); in <- y + 0.75*dt*k2
        e.kdst = k2; e.c = 0.75f * dt;
        layer<K0, WW, 8,  8, 4, 0>(in_sm, K0, g_W0p, b0, h1, wtile, tid, e);
        layer<WW, WW, 32, 8, 4, 0>(h1,    WW, g_W1p, b1, h2, wtile, tid, e);
        layer<WW, LL, 64, 4, 2, 1>(h2,    WW, g_W2p, b2, nullptr, wtile, tid, e);

        // stage 2: k3 = f(in); y <- y + dt*(2/9 k1 + 1/3 k2 + 4/9 k3); save
        e.d1 = dt * (2.0f / 9.0f);
        e.d2 = dt * (1.0f / 3.0f);
        e.d3 = dt * (4.0f / 9.0f);
        e.outp = out + (size_t)row0g * (TT * LL) + (size_t)(t + 1) * LL;
        layer<K0, WW, 8,  8, 4, 0>(in_sm, K0, g_W0p, b0, h1, wtile, tid, e);
        layer<WW, WW, 32, 8, 4, 0>(h1,    WW, g_W1p, b1, h2, wtile, tid, e);
        layer<WW, LL, 64, 4, 2, 2>(h2,    WW, g_W2p, b2, nullptr, wtile, tid, e);
    }
}

// ---------------------------------------------------------------------------
extern "C" void kernel_launch(void* const* d_in, const int* in_sizes, int n_in,
                              void* d_out, int out_size) {
    (void)in_sizes; (void)n_in; (void)out_size;
    const float* x0   = (const float*)d_in[0];
    const float* ts   = (const float*)d_in[1];
    const float* args = (const float*)d_in[2];
    const float* W0   = (const float*)d_in[3];
    const float* b0   = (const float*)d_in[4];
    const float* W1   = (const float*)d_in[5];
    const float* b1   = (const float*)d_in[6];
    const float* W2   = (const float*)d_in[7];
    const float* b2   = (const float*)d_in[8];
    float* out = (float*)d_out;

    const int total = K0 * WW + WW * WW + WW * LL;
    transform_kernel<<<(total + 255) / 256, 256>>>(W0, W1, W2);

    cudaFuncSetAttribute(ode_kernel, cudaFuncAttributeMaxDynamicSharedMemorySize,
                         SMEM_BYTES);
    ode_kernel<<<NCTAS, NTHREADS, SMEM_BYTES>>>(x0, ts, args, b0, b1, b2, out);
}